// round 14
// baseline (speedup 1.0000x reference)
#include <cuda_runtime.h>
#include <cuda_fp16.h>
#include <cstdint>

#define Bsz 512
#define Nn  98
#define DIM 512
#define NH  16
#define HD  32
#define Mrows (Bsz*Nn)
#define QKV_N (3*DIM)
#define SCALE 0.17677669529663687f
#define XELEMS ((size_t)Mrows*DIM)

#define KT 128
#define TILE_B (128*272)           // 34816
#define STAGE_B (2*TILE_B)         // 69632
#define SMEM_GEMM (2*STAGE_B)      // 139264

#define W_QKV (QKV_N*DIM)
#define W_PROJ (DIM*DIM)
#define BIAS_T (NH*Nn*Nn)
#define PREP_TOT (W_QKV + W_PROJ + BIAS_T)

// attention smem layout (bytes)
#define OQ 0
#define OK2 8960
#define OV 17920
#define OP 26880                 // 112 rows x 224 B (fp16 P)
#define OB 51968                 // 98 rows x 208 B (fp16 bias)
#define SMEM_ATTN (OB + 98*208)  // 72352

// ---------------- scratch ----------------------------------------------------
__device__ __half g_q[(size_t)Bsz*NH*Nn*HD];
__device__ __half g_k[(size_t)Bsz*NH*Nn*HD];
__device__ __half g_v[(size_t)Bsz*NH*Nn*HD];
__device__ __half g_xh[XELEMS];
__device__ __half g_ah[XELEMS];
__device__ __half g_wqh[(size_t)QKV_N*DIM];
__device__ __half g_wph[(size_t)DIM*DIM];
__device__ __half g_bias_ph[NH*Nn*104];   // padded fp16 bias [h][r][104]

// ---------------- helpers ----------------------------------------------------
__device__ __forceinline__ uint32_t smem_u32(const void* p) {
    uint32_t a;
    asm("{ .reg .u64 t; cvta.to.shared.u64 t, %1; cvt.u32.u64 %0, t; }"
        : "=r"(a) : "l"(p));
    return a;
}
__device__ __forceinline__ void cp16(uint32_t s, const void* g) {
    asm volatile("cp.async.cg.shared.global [%0], [%1], 16;" :: "r"(s), "l"(g));
}
__device__ __forceinline__ void ldsm4(uint32_t& r0, uint32_t& r1, uint32_t& r2,
                                      uint32_t& r3, uint32_t a) {
    asm volatile("ldmatrix.sync.aligned.m8n8.x4.shared.b16 {%0,%1,%2,%3}, [%4];"
                 : "=r"(r0), "=r"(r1), "=r"(r2), "=r"(r3) : "r"(a));
}
__device__ __forceinline__ void ldsm4t(uint32_t& r0, uint32_t& r1, uint32_t& r2,
                                       uint32_t& r3, uint32_t a) {
    asm volatile("ldmatrix.sync.aligned.m8n8.x4.trans.shared.b16 {%0,%1,%2,%3}, [%4];"
                 : "=r"(r0), "=r"(r1), "=r"(r2), "=r"(r3) : "r"(a));
}
__device__ __forceinline__ void sts128(uint32_t a, uint4 v) {
    asm volatile("st.shared.v4.b32 [%0], {%1,%2,%3,%4};"
                 :: "r"(a), "r"(v.x), "r"(v.y), "r"(v.z), "r"(v.w) : "memory");
}
__device__ __forceinline__ void mma4(float* d, const uint32_t* a, const uint32_t* b) {
    asm volatile("mma.sync.aligned.m16n8k16.row.col.f32.f16.f16.f32 "
                 "{%0,%1,%2,%3}, {%4,%5,%6,%7}, {%8,%9}, {%0,%1,%2,%3};"
                 : "+f"(d[0]), "+f"(d[1]), "+f"(d[2]), "+f"(d[3])
                 : "r"(a[0]), "r"(a[1]), "r"(a[2]), "r"(a[3]), "r"(b[0]), "r"(b[1]));
}
__device__ __forceinline__ uint32_t packh2(__half a, __half b) {
    __half2 t = __halves2half2(a, b);
    return reinterpret_cast<uint32_t&>(t);
}

// ---------------- conversion / prep kernels ---------------------------------
__global__ __launch_bounds__(256) void conv_x_kernel(const float* __restrict__ x) {
    size_t i = (size_t)blockIdx.x * 256 + threadIdx.x;
    if (i >= XELEMS / 4) return;
    float4 v = ((const float4*)x)[i];
    ((uint2*)g_xh)[i] = make_uint2(
        packh2(__float2half(v.x), __float2half(v.y)),
        packh2(__float2half(v.z), __float2half(v.w)));
}

__global__ __launch_bounds__(256) void prep_kernel(const float* __restrict__ wq,
                                                   const float* __restrict__ wp,
                                                   const float* __restrict__ bt,
                                                   const int* __restrict__ ri) {
    int idx = blockIdx.x * 256 + threadIdx.x;
    if (idx < W_QKV) {
        int n = idx >> 9, k = idx & 511;
        g_wqh[idx] = __float2half(wq[(size_t)k * QKV_N + n]);
    } else if (idx < W_QKV + W_PROJ) {
        int i2 = idx - W_QKV;
        int n = i2 >> 9, k = i2 & 511;
        g_wph[i2] = __float2half(wp[(size_t)k * DIM + n]);
    } else if (idx < PREP_TOT) {
        int i2 = idx - W_QKV - W_PROJ;
        int h = i2 / (Nn * Nn);
        int t = i2 - h * (Nn * Nn);
        int r = t / Nn, c = t - r * Nn;
        g_bias_ph[(h * Nn + r) * 104 + c] = __float2half(bt[ri[t] * NH + h]);
    }
}

// ---------------- HMMA GEMM: 128x128 tile, KT=128, depth-1 overlap ----------
template<bool IS_QKV>
__global__ __launch_bounds__(256) void gemm_kernel(const float* __restrict__ bias,
                                                   float* __restrict__ outp) {
    extern __shared__ __align__(16) char smraw[];
    const uint32_t sbase = smem_u32(smraw);
    const int tid = threadIdx.x;
    const int wid = tid >> 5, l = tid & 31;
    const int bm = blockIdx.y * 128, bn = blockIdx.x * 128;
    const int wm = wid & 1, wn = wid >> 1;   // warp tile: 64(M) x 32(N)

    const __half* __restrict__ Ah = IS_QKV ? g_xh : g_ah;
    const __half* __restrict__ Bh = IS_QKV ? g_wqh : g_wph;

    auto issue = [&](int st, int ck) {
        const int k0 = ck * KT;
        const uint32_t base = sbase + st * STAGE_B;
#pragma unroll
        for (int i = 0; i < 8; i++) {
            const int idx = i * 256 + tid;          // 0..2047
            const int row = idx >> 4, c = idx & 15;
            cp16(base + row * 272 + c * 16,
                 Ah + (size_t)(bm + row) * 512 + k0 + c * 8);
            cp16(base + TILE_B + row * 272 + c * 16,
                 Bh + (size_t)(bn + row) * 512 + k0 + c * 8);
        }
        asm volatile("cp.async.commit_group;" ::: "memory");
    };

    float acc[4][4][4];
#pragma unroll
    for (int a = 0; a < 4; a++)
#pragma unroll
        for (int b = 0; b < 4; b++)
#pragma unroll
            for (int c = 0; c < 4; c++) acc[a][b][c] = 0.f;

    uint32_t af[2][4][4], bf[2][4][2];

    auto load_frags = [&](int buf, uint32_t base, int ks) {
#pragma unroll
        for (int mi = 0; mi < 4; mi++) {
            uint32_t ad = base + (uint32_t)(wm * 64 + mi * 16 + (l & 15)) * 272
                        + (uint32_t)(ks * 32 + (l >> 4) * 16);
            ldsm4(af[buf][mi][0], af[buf][mi][1], af[buf][mi][2], af[buf][mi][3], ad);
        }
#pragma unroll
        for (int p = 0; p < 2; p++) {
            uint32_t nrow = (uint32_t)(wn * 32 + p * 16 + (l >> 4) * 8 + (l & 7));
            uint32_t bd = base + TILE_B + nrow * 272
                        + (uint32_t)(ks * 32 + ((l >> 3) & 1) * 16);
            uint32_t r0, r1, r2, r3;
            ldsm4(r0, r1, r2, r3, bd);
            bf[buf][2*p][0] = r0; bf[buf][2*p][1] = r1;
            bf[buf][2*p+1][0] = r2; bf[buf][2*p+1][1] = r3;
        }
    };

    issue(0, 0);

    for (int ck = 0; ck < 4; ck++) {
        asm volatile("cp.async.wait_group 0;" ::: "memory");
        __syncthreads();
        if (ck + 1 < 4) issue((ck + 1) & 1, ck + 1);   // overlaps compute below

        const uint32_t base = sbase + (ck & 1) * STAGE_B;
        load_frags(0, base, 0);
#pragma unroll
        for (int ks = 0; ks < 8; ks++) {
            if (ks < 7) load_frags((ks + 1) & 1, base, ks + 1);
            const int buf = ks & 1;
#pragma unroll
            for (int mi = 0; mi < 4; mi++)
#pragma unroll
                for (int ni = 0; ni < 4; ni++)
                    mma4(acc[mi][ni], af[buf][mi], bf[buf][ni]);
        }
    }

    // -------- epilogue --------
    if (IS_QKV) {
        const int which = bn >> 9;
        const int h = ((bn >> 5) + wn) & (NH - 1);
        __half* dst0 = which == 0 ? g_q : which == 1 ? g_k : g_v;
        const float sc = which == 0 ? SCALE : 1.f;
        const float* bptr = bias + which * 512 + h * 32;
#pragma unroll
        for (int mi = 0; mi < 4; mi++) {
#pragma unroll
            for (int rr = 0; rr < 2; rr++) {
                int m = bm + wm * 64 + mi * 16 + (l >> 2) + rr * 8;
                int b = m / Nn, r = m - b * Nn;
                __half* rowp = dst0 + ((size_t)(b * NH + h) * Nn + r) * HD;
#pragma unroll
                for (int ni = 0; ni < 4; ni++) {
                    int hd = ni * 8 + 2 * (l & 3);
                    float v0 = (acc[mi][ni][rr * 2 + 0] + bptr[hd])     * sc;
                    float v1 = (acc[mi][ni][rr * 2 + 1] + bptr[hd + 1]) * sc;
                    *(__half2*)(rowp + hd) = __floats2half2_rn(v0, v1);
                }
            }
        }
    } else {
        const int nb = bn + wn * 32;
#pragma unroll
        for (int mi = 0; mi < 4; mi++) {
#pragma unroll
            for (int rr = 0; rr < 2; rr++) {
                int m = bm + wm * 64 + mi * 16 + (l >> 2) + rr * 8;
                float* rowp = outp + (size_t)m * DIM + nb;
#pragma unroll
                for (int ni = 0; ni < 4; ni++) {
                    int off = ni * 8 + 2 * (l & 3);
                    float v0 = acc[mi][ni][rr * 2 + 0] + bias[nb + off];
                    float v1 = acc[mi][ni][rr * 2 + 1] + bias[nb + off + 1];
                    *(float2*)(rowp + off) = make_float2(v0, v1);
                }
            }
        }
    }
}

// ---------------- MMA attention (R12 version, unchanged) ---------------------
__global__ __launch_bounds__(128) void attn_kernel() {
    extern __shared__ __align__(16) char smem[];
    const uint32_t sb = smem_u32(smem);
    const int tid = threadIdx.x;
    const int wid = tid >> 5, l = tid & 31;
    const int bh = blockIdx.x;
    const int h = bh & (NH - 1);
    const int b = bh >> 4;

    const __half* qg = g_q + (size_t)bh * Nn * HD;
    const __half* kg = g_k + (size_t)bh * Nn * HD;
    const __half* vg = g_v + (size_t)bh * Nn * HD;
    for (int t = tid; t < 392; t += 128) {
        int row = t >> 2, c = t & 3;
        cp16(sb + OQ  + row * 80 + c * 16, qg + row * 32 + c * 8);
        cp16(sb + OK2 + row * 80 + c * 16, kg + row * 32 + c * 8);
        cp16(sb + OV  + row * 80 + c * 16, vg + row * 32 + c * 8);
    }
    const __half* bg = g_bias_ph + (size_t)h * Nn * 104;
    for (int t = tid; t < 1274; t += 128) {
        int row = t / 13, c16 = t - row * 13;
        cp16(sb + OB + row * 208 + c16 * 16, bg + row * 104 + c16 * 8);
    }
    asm volatile("cp.async.commit_group;" ::: "memory");
    for (int t = tid; t < 56; t += 128) {
        int row = 98 + (t >> 2), c = t & 3;
        sts128(sb + OV + row * 80 + c * 16, make_uint4(0, 0, 0, 0));
    }
    for (int r = tid; r < 112; r += 128)
        sts128(sb + OP + r * 224 + 208, make_uint4(0, 0, 0, 0));
    asm volatile("cp.async.wait_group 0;" ::: "memory");
    __syncthreads();

    float accS[2][13][4];
#pragma unroll
    for (int t = 0; t < 2; t++)
#pragma unroll
        for (int n = 0; n < 13; n++)
#pragma unroll
            for (int c = 0; c < 4; c++) accS[t][n][c] = 0.f;

#pragma unroll
    for (int ks = 0; ks < 2; ks++) {
        uint32_t aS[2][4];
#pragma unroll
        for (int t = 0; t < 2; t++) {
            int mt = wid * 2 + t;
            if (mt < 7) {
                uint32_t ad = sb + OQ + (uint32_t)(mt * 16 + (l & 15)) * 80
                            + (uint32_t)(ks * 2 + (l >> 4)) * 16;
                ldsm4(aS[t][0], aS[t][1], aS[t][2], aS[t][3], ad);
            }
        }
        uint32_t bS[13][2];
#pragma unroll
        for (int p = 0; p < 7; p++) {
            uint32_t bd = sb + OK2 + (uint32_t)(p * 16 + (l >> 4) * 8 + (l & 7)) * 80
                        + (uint32_t)(ks * 2 + ((l >> 3) & 1)) * 16;
            uint32_t r0, r1, r2, r3;
            ldsm4(r0, r1, r2, r3, bd);
            bS[2*p][0] = r0; bS[2*p][1] = r1;
            if (2*p + 1 < 13) { bS[2*p+1][0] = r2; bS[2*p+1][1] = r3; }
        }
#pragma unroll
        for (int t = 0; t < 2; t++) {
            int mt = wid * 2 + t;
            if (mt < 7)
#pragma unroll
                for (int ni = 0; ni < 13; ni++)
                    mma4(accS[t][ni], aS[t], bS[ni]);
        }
    }

    float invv[2][2];
#pragma unroll
    for (int t = 0; t < 2; t++) {
        int mt = wid * 2 + t;
        if (mt >= 7) continue;
#pragma unroll
        for (int rr = 0; rr < 2; rr++) {
            int r = mt * 16 + (l >> 2) + rr * 8;
            float mx = -1e30f;
#pragma unroll
            for (int ni = 0; ni < 13; ni++) {
                int c = ni * 8 + 2 * (l & 3);
                float b0 = 0.f, b1 = 0.f;
                if (r < 98 && c < 98) {
                    uint32_t braw;
                    asm volatile("ld.shared.b32 %0, [%1];"
                                 : "=r"(braw)
                                 : "r"(sb + OB + (uint32_t)(r * 208 + c * 2)));
                    float2 bb = __half22float2(reinterpret_cast<__half2&>(braw));
                    b0 = bb.x; b1 = bb.y;
                }
                float s0 = accS[t][ni][rr * 2 + 0] + b0;
                float s1 = accS[t][ni][rr * 2 + 1] + b1;
                accS[t][ni][rr * 2 + 0] = s0;
                accS[t][ni][rr * 2 + 1] = s1;
                if (c < 98) mx = fmaxf(mx, fmaxf(s0, s1));
            }
            mx = fmaxf(mx, __shfl_xor_sync(0xFFFFFFFF, mx, 1));
            mx = fmaxf(mx, __shfl_xor_sync(0xFFFFFFFF, mx, 2));
            float sum = 0.f;
#pragma unroll
            for (int ni = 0; ni < 13; ni++) {
                int c = ni * 8 + 2 * (l & 3);
                float e0 = 0.f, e1 = 0.f;
                if (c < 98) {
                    e0 = __expf(accS[t][ni][rr * 2 + 0] - mx);
                    e1 = __expf(accS[t][ni][rr * 2 + 1] - mx);
                }
                sum += e0 + e1;
                uint32_t pk = packh2(__float2half(e0), __float2half(e1));
                asm volatile("st.shared.b32 [%0], %1;"
                             :: "r"(sb + OP + (uint32_t)(r * 224 + c * 2)), "r"(pk)
                             : "memory");
            }
            sum += __shfl_xor_sync(0xFFFFFFFF, sum, 1);
            sum += __shfl_xor_sync(0xFFFFFFFF, sum, 2);
            invv[t][rr] = 1.f / sum;
        }
    }
    __syncthreads();

    float accO[2][4][4];
#pragma unroll
    for (int t = 0; t < 2; t++)
#pragma unroll
        for (int n = 0; n < 4; n++)
#pragma unroll
            for (int c = 0; c < 4; c++) accO[t][n][c] = 0.f;

#pragma unroll
    for (int kst = 0; kst < 7; kst++) {
        uint32_t aO[2][4];
#pragma unroll
        for (int t = 0; t < 2; t++) {
            int mt = wid * 2 + t;
            if (mt < 7) {
                uint32_t ad = sb + OP + (uint32_t)(mt * 16 + (l & 15)) * 224
                            + (uint32_t)(kst * 2 + (l >> 4)) * 16;
                ldsm4(aO[t][0], aO[t][1], aO[t][2], aO[t][3], ad);
            }
        }
        uint32_t bO[4][2];
#pragma unroll
        for (int half = 0; half < 2; half++) {
            uint32_t bd = sb + OV
                        + (uint32_t)(kst * 16 + (l & 7) + ((l >> 3) & 1) * 8) * 80
                        + (uint32_t)((l >> 4) * 8 + half * 16) * 2;
            uint32_t r0, r1, r2, r3;
            ldsm4t(r0, r1, r2, r3, bd);
            bO[2*half][0] = r0;   bO[2*half][1] = r1;
            bO[2*half+1][0] = r2; bO[2*half+1][1] = r3;
        }
#pragma unroll
        for (int t = 0; t < 2; t++) {
            int mt = wid * 2 + t;
            if (mt < 7)
#pragma unroll
                for (int ni = 0; ni < 4; ni++)
                    mma4(accO[t][ni], aO[t], bO[ni]);
        }
    }

#pragma unroll
    for (int t = 0; t < 2; t++) {
        int mt = wid * 2 + t;
        if (mt >= 7) continue;
#pragma unroll
        for (int rr = 0; rr < 2; rr++) {
            int r = mt * 16 + (l >> 2) + rr * 8;
            if (r >= 98) continue;
            float inv = invv[t][rr];
            __half* orow = g_ah + ((size_t)b * Nn + r) * DIM + h * HD;
#pragma unroll
            for (int ni = 0; ni < 4; ni++) {
                int c = ni * 8 + 2 * (l & 3);
                *(__half2*)(orow + c) =
                    __floats2half2_rn(accO[t][ni][rr * 2 + 0] * inv,
                                      accO[t][ni][rr * 2 + 1] * inv);
            }
        }
    }
}

// ---------------- launch -----------------------------------------------------
extern "C" void kernel_launch(void* const* d_in, const int* in_sizes, int n_in,
                              void* d_out, int out_size) {
    const float* x          = (const float*)d_in[0];
    const float* qkv_w      = (const float*)d_in[1];
    const float* qkv_b      = (const float*)d_in[2];
    const float* proj_w     = (const float*)d_in[3];
    const float* proj_b     = (const float*)d_in[4];
    const float* bias_table = (const float*)d_in[5];
    const int*   rel_index  = (const int*)d_in[6];
    float*       out        = (float*)d_out;

    static bool inited = false;
    if (!inited) {
        cudaFuncSetAttribute(gemm_kernel<true>,
                             cudaFuncAttributeMaxDynamicSharedMemorySize, SMEM_GEMM);
        cudaFuncSetAttribute(gemm_kernel<false>,
                             cudaFuncAttributeMaxDynamicSharedMemorySize, SMEM_GEMM);
        cudaFuncSetAttribute(attn_kernel,
                             cudaFuncAttributeMaxDynamicSharedMemorySize, SMEM_ATTN);
        inited = true;
    }

    conv_x_kernel<<<(int)((XELEMS / 4 + 255) / 256), 256>>>(x);
    prep_kernel<<<(PREP_TOT + 255) / 256, 256>>>(qkv_w, proj_w, bias_table, rel_index);
    gemm_kernel<true><<<dim3(QKV_N / 128, Mrows / 128), 256, SMEM_GEMM>>>(qkv_b, nullptr);
    attn_kernel<<<Bsz * NH, 128, SMEM_ATTN>>>();
    gemm_kernel<false><<<dim3(DIM / 128, Mrows / 128), 256, SMEM_GEMM>>>(proj_b, out);
}

// round 15
// speedup vs baseline: 1.2254x; 1.2254x over previous
#include <cuda_runtime.h>
#include <cuda_fp16.h>
#include <cstdint>

#define Bsz 512
#define Nn  98
#define DIM 512
#define NH  16
#define HD  32
#define Mrows (Bsz*Nn)
#define QKV_N (3*DIM)
#define SCALE 0.17677669529663687f
#define XELEMS ((size_t)Mrows*DIM)

#define KT 64
#define NSTAGE 3
#define TILE_B (128*144)          // 18432
#define STAGE_B (2*TILE_B)        // 36864
#define SMEM_GEMM (NSTAGE*STAGE_B) // 110592

#define W_QKV (QKV_N*DIM)
#define W_PROJ (DIM*DIM)
#define BIAS_T (NH*Nn*Nn)
#define PREP_TOT (W_QKV + W_PROJ + BIAS_T)

// attention smem layout (bytes)
#define OQ 0
#define OK2 8960
#define OV 17920
#define OP 26880                 // 112 rows x 240 B (fp16 P, odd-16B pitch)
#define OB 53760                 // 98 rows x 208 B (fp16 bias)
#define SMEM_ATTN (OB + 98*208)  // 74144

// ---------------- scratch ----------------------------------------------------
__device__ __half g_q[(size_t)Bsz*NH*Nn*HD];
__device__ __half g_k[(size_t)Bsz*NH*Nn*HD];
__device__ __half g_v[(size_t)Bsz*NH*Nn*HD];
__device__ __half g_xh[XELEMS];
__device__ __half g_ah[XELEMS];
__device__ __half g_wqh[(size_t)QKV_N*DIM];
__device__ __half g_wph[(size_t)DIM*DIM];
__device__ __half g_bias_ph[NH*Nn*104];   // padded fp16 bias [h][r][104]

// ---------------- helpers ----------------------------------------------------
__device__ __forceinline__ uint32_t smem_u32(const void* p) {
    uint32_t a;
    asm("{ .reg .u64 t; cvta.to.shared.u64 t, %1; cvt.u32.u64 %0, t; }"
        : "=r"(a) : "l"(p));
    return a;
}
__device__ __forceinline__ void cp16(uint32_t s, const void* g) {
    asm volatile("cp.async.cg.shared.global [%0], [%1], 16;" :: "r"(s), "l"(g));
}
__device__ __forceinline__ void ldsm4(uint32_t& r0, uint32_t& r1, uint32_t& r2,
                                      uint32_t& r3, uint32_t a) {
    asm volatile("ldmatrix.sync.aligned.m8n8.x4.shared.b16 {%0,%1,%2,%3}, [%4];"
                 : "=r"(r0), "=r"(r1), "=r"(r2), "=r"(r3) : "r"(a));
}
__device__ __forceinline__ void ldsm4t(uint32_t& r0, uint32_t& r1, uint32_t& r2,
                                       uint32_t& r3, uint32_t a) {
    asm volatile("ldmatrix.sync.aligned.m8n8.x4.trans.shared.b16 {%0,%1,%2,%3}, [%4];"
                 : "=r"(r0), "=r"(r1), "=r"(r2), "=r"(r3) : "r"(a));
}
__device__ __forceinline__ void sts128(uint32_t a, uint4 v) {
    asm volatile("st.shared.v4.b32 [%0], {%1,%2,%3,%4};"
                 :: "r"(a), "r"(v.x), "r"(v.y), "r"(v.z), "r"(v.w) : "memory");
}
__device__ __forceinline__ void mma4(float* d, const uint32_t* a, const uint32_t* b) {
    asm volatile("mma.sync.aligned.m16n8k16.row.col.f32.f16.f16.f32 "
                 "{%0,%1,%2,%3}, {%4,%5,%6,%7}, {%8,%9}, {%0,%1,%2,%3};"
                 : "+f"(d[0]), "+f"(d[1]), "+f"(d[2]), "+f"(d[3])
                 : "r"(a[0]), "r"(a[1]), "r"(a[2]), "r"(a[3]), "r"(b[0]), "r"(b[1]));
}
__device__ __forceinline__ uint32_t packh2(__half a, __half b) {
    __half2 t = __halves2half2(a, b);
    return reinterpret_cast<uint32_t&>(t);
}

// ---------------- conversion / prep kernels ---------------------------------
__global__ __launch_bounds__(256) void conv_x_kernel(const float* __restrict__ x) {
    size_t i = (size_t)blockIdx.x * 256 + threadIdx.x;
    if (i >= XELEMS / 4) return;
    float4 v = ((const float4*)x)[i];
    ((uint2*)g_xh)[i] = make_uint2(
        packh2(__float2half(v.x), __float2half(v.y)),
        packh2(__float2half(v.z), __float2half(v.w)));
}

__global__ __launch_bounds__(256) void prep_kernel(const float* __restrict__ wq,
                                                   const float* __restrict__ wp,
                                                   const float* __restrict__ bt,
                                                   const int* __restrict__ ri) {
    int idx = blockIdx.x * 256 + threadIdx.x;
    if (idx < W_QKV) {
        int n = idx >> 9, k = idx & 511;
        g_wqh[idx] = __float2half(wq[(size_t)k * QKV_N + n]);
    } else if (idx < W_QKV + W_PROJ) {
        int i2 = idx - W_QKV;
        int n = i2 >> 9, k = i2 & 511;
        g_wph[i2] = __float2half(wp[(size_t)k * DIM + n]);
    } else if (idx < PREP_TOT) {
        int i2 = idx - W_QKV - W_PROJ;
        int h = i2 / (Nn * Nn);
        int t = i2 - h * (Nn * Nn);
        int r = t / Nn, c = t - r * Nn;
        g_bias_ph[(h * Nn + r) * 104 + c] = __float2half(bt[ri[t] * NH + h]);
    }
}

// ---------------- HMMA GEMM (R13 exact: KT=64, NSTAGE=3, frag dbl-buffer) ---
template<bool IS_QKV>
__global__ __launch_bounds__(256) void gemm_kernel(const float* __restrict__ bias,
                                                   float* __restrict__ outp) {
    extern __shared__ __align__(16) char smraw[];
    const uint32_t sbase = smem_u32(smraw);
    const int tid = threadIdx.x;
    const int wid = tid >> 5, l = tid & 31;
    const int bm = blockIdx.y * 128, bn = blockIdx.x * 128;
    const int wm = wid & 1, wn = wid >> 1;   // warp tile: 64(M) x 32(N)

    const __half* __restrict__ Ah = IS_QKV ? g_xh : g_ah;
    const __half* __restrict__ Bh = IS_QKV ? g_wqh : g_wph;

    auto issue = [&](int st, int ck) {
        const int k0 = ck * KT;
        const uint32_t base = sbase + st * STAGE_B;
#pragma unroll
        for (int i = 0; i < 4; i++) {
            const int idx = i * 256 + tid;
            const int row = idx >> 3, c = idx & 7;
            cp16(base + row * 144 + c * 16,
                 Ah + (size_t)(bm + row) * 512 + k0 + c * 8);
            cp16(base + TILE_B + row * 144 + c * 16,
                 Bh + (size_t)(bn + row) * 512 + k0 + c * 8);
        }
        asm volatile("cp.async.commit_group;" ::: "memory");
    };

    float acc[4][4][4];
#pragma unroll
    for (int a = 0; a < 4; a++)
#pragma unroll
        for (int b = 0; b < 4; b++)
#pragma unroll
            for (int c = 0; c < 4; c++) acc[a][b][c] = 0.f;

    uint32_t af[2][4][4], bf[2][4][2];

    auto load_frags = [&](int buf, uint32_t base, int ks) {
#pragma unroll
        for (int mi = 0; mi < 4; mi++) {
            uint32_t ad = base + (uint32_t)(wm * 64 + mi * 16 + (l & 15)) * 144
                        + (uint32_t)(ks * 32 + (l >> 4) * 16);
            ldsm4(af[buf][mi][0], af[buf][mi][1], af[buf][mi][2], af[buf][mi][3], ad);
        }
#pragma unroll
        for (int p = 0; p < 2; p++) {
            uint32_t nrow = (uint32_t)(wn * 32 + p * 16 + (l >> 4) * 8 + (l & 7));
            uint32_t bd = base + TILE_B + nrow * 144
                        + (uint32_t)(ks * 32 + ((l >> 3) & 1) * 16);
            uint32_t r0, r1, r2, r3;
            ldsm4(r0, r1, r2, r3, bd);
            bf[buf][2*p][0] = r0; bf[buf][2*p][1] = r1;
            bf[buf][2*p+1][0] = r2; bf[buf][2*p+1][1] = r3;
        }
    };

    issue(0, 0);
    issue(1, 1);

    for (int ck = 0; ck < 8; ck++) {
        if (ck < 7) asm volatile("cp.async.wait_group 1;" ::: "memory");
        else        asm volatile("cp.async.wait_group 0;" ::: "memory");
        __syncthreads();
        if (ck + 2 < 8) issue((ck + 2) % NSTAGE, ck + 2);

        const uint32_t base = sbase + (ck % NSTAGE) * STAGE_B;
        load_frags(0, base, 0);
#pragma unroll
        for (int ks = 0; ks < 4; ks++) {
            if (ks < 3) load_frags((ks + 1) & 1, base, ks + 1);
            const int buf = ks & 1;
#pragma unroll
            for (int mi = 0; mi < 4; mi++)
#pragma unroll
                for (int ni = 0; ni < 4; ni++)
                    mma4(acc[mi][ni], af[buf][mi], bf[buf][ni]);
        }
    }

    // -------- epilogue --------
    if (IS_QKV) {
        const int which = bn >> 9;
        const int h = ((bn >> 5) + wn) & (NH - 1);
        __half* dst0 = which == 0 ? g_q : which == 1 ? g_k : g_v;
        const float sc = which == 0 ? SCALE : 1.f;
        const float* bptr = bias + which * 512 + h * 32;
#pragma unroll
        for (int mi = 0; mi < 4; mi++) {
#pragma unroll
            for (int rr = 0; rr < 2; rr++) {
                int m = bm + wm * 64 + mi * 16 + (l >> 2) + rr * 8;
                int b = m / Nn, r = m - b * Nn;
                __half* rowp = dst0 + ((size_t)(b * NH + h) * Nn + r) * HD;
#pragma unroll
                for (int ni = 0; ni < 4; ni++) {
                    int hd = ni * 8 + 2 * (l & 3);
                    float v0 = (acc[mi][ni][rr * 2 + 0] + bptr[hd])     * sc;
                    float v1 = (acc[mi][ni][rr * 2 + 1] + bptr[hd + 1]) * sc;
                    *(__half2*)(rowp + hd) = __floats2half2_rn(v0, v1);
                }
            }
        }
    } else {
        const int nb = bn + wn * 32;
#pragma unroll
        for (int mi = 0; mi < 4; mi++) {
#pragma unroll
            for (int rr = 0; rr < 2; rr++) {
                int m = bm + wm * 64 + mi * 16 + (l >> 2) + rr * 8;
                float* rowp = outp + (size_t)m * DIM + nb;
#pragma unroll
                for (int ni = 0; ni < 4; ni++) {
                    int off = ni * 8 + 2 * (l & 3);
                    float v0 = acc[mi][ni][rr * 2 + 0] + bias[nb + off];
                    float v1 = acc[mi][ni][rr * 2 + 1] + bias[nb + off + 1];
                    *(float2*)(rowp + off) = make_float2(v0, v1);
                }
            }
        }
    }
}

// ---------------- MMA attention (R12 + conflict-free P pitch 240) ------------
__global__ __launch_bounds__(128) void attn_kernel() {
    extern __shared__ __align__(16) char smem[];
    const uint32_t sb = smem_u32(smem);
    const int tid = threadIdx.x;
    const int wid = tid >> 5, l = tid & 31;
    const int bh = blockIdx.x;
    const int h = bh & (NH - 1);
    const int b = bh >> 4;

    const __half* qg = g_q + (size_t)bh * Nn * HD;
    const __half* kg = g_k + (size_t)bh * Nn * HD;
    const __half* vg = g_v + (size_t)bh * Nn * HD;
    for (int t = tid; t < 392; t += 128) {
        int row = t >> 2, c = t & 3;
        cp16(sb + OQ  + row * 80 + c * 16, qg + row * 32 + c * 8);
        cp16(sb + OK2 + row * 80 + c * 16, kg + row * 32 + c * 8);
        cp16(sb + OV  + row * 80 + c * 16, vg + row * 32 + c * 8);
    }
    const __half* bg = g_bias_ph + (size_t)h * Nn * 104;
    for (int t = tid; t < 1274; t += 128) {
        int row = t / 13, c16 = t - row * 13;
        cp16(sb + OB + row * 208 + c16 * 16, bg + row * 104 + c16 * 8);
    }
    asm volatile("cp.async.commit_group;" ::: "memory");
    for (int t = tid; t < 56; t += 128) {
        int row = 98 + (t >> 2), c = t & 3;
        sts128(sb + OV + row * 80 + c * 16, make_uint4(0, 0, 0, 0));
    }
    for (int r = tid; r < 112; r += 128)
        sts128(sb + OP + r * 240 + 208, make_uint4(0, 0, 0, 0));
    asm volatile("cp.async.wait_group 0;" ::: "memory");
    __syncthreads();

    float accS[2][13][4];
#pragma unroll
    for (int t = 0; t < 2; t++)
#pragma unroll
        for (int n = 0; n < 13; n++)
#pragma unroll
            for (int c = 0; c < 4; c++) accS[t][n][c] = 0.f;

#pragma unroll
    for (int ks = 0; ks < 2; ks++) {
        uint32_t aS[2][4];
#pragma unroll
        for (int t = 0; t < 2; t++) {
            int mt = wid * 2 + t;
            if (mt < 7) {
                uint32_t ad = sb + OQ + (uint32_t)(mt * 16 + (l & 15)) * 80
                            + (uint32_t)(ks * 2 + (l >> 4)) * 16;
                ldsm4(aS[t][0], aS[t][1], aS[t][2], aS[t][3], ad);
            }
        }
        uint32_t bS[13][2];
#pragma unroll
        for (int p = 0; p < 7; p++) {
            uint32_t bd = sb + OK2 + (uint32_t)(p * 16 + (l >> 4) * 8 + (l & 7)) * 80
                        + (uint32_t)(ks * 2 + ((l >> 3) & 1)) * 16;
            uint32_t r0, r1, r2, r3;
            ldsm4(r0, r1, r2, r3, bd);
            bS[2*p][0] = r0; bS[2*p][1] = r1;
            if (2*p + 1 < 13) { bS[2*p+1][0] = r2; bS[2*p+1][1] = r3; }
        }
#pragma unroll
        for (int t = 0; t < 2; t++) {
            int mt = wid * 2 + t;
            if (mt < 7)
#pragma unroll
                for (int ni = 0; ni < 13; ni++)
                    mma4(accS[t][ni], aS[t], bS[ni]);
        }
    }

    float invv[2][2];
#pragma unroll
    for (int t = 0; t < 2; t++) {
        int mt = wid * 2 + t;
        if (mt >= 7) continue;
#pragma unroll
        for (int rr = 0; rr < 2; rr++) {
            int r = mt * 16 + (l >> 2) + rr * 8;
            float mx = -1e30f;
#pragma unroll
            for (int ni = 0; ni < 13; ni++) {
                int c = ni * 8 + 2 * (l & 3);
                float b0 = 0.f, b1 = 0.f;
                if (r < 98 && c < 98) {
                    uint32_t braw;
                    asm volatile("ld.shared.b32 %0, [%1];"
                                 : "=r"(braw)
                                 : "r"(sb + OB + (uint32_t)(r * 208 + c * 2)));
                    float2 bb = __half22float2(reinterpret_cast<__half2&>(braw));
                    b0 = bb.x; b1 = bb.y;
                }
                float s0 = accS[t][ni][rr * 2 + 0] + b0;
                float s1 = accS[t][ni][rr * 2 + 1] + b1;
                accS[t][ni][rr * 2 + 0] = s0;
                accS[t][ni][rr * 2 + 1] = s1;
                if (c < 98) mx = fmaxf(mx, fmaxf(s0, s1));
            }
            mx = fmaxf(mx, __shfl_xor_sync(0xFFFFFFFF, mx, 1));
            mx = fmaxf(mx, __shfl_xor_sync(0xFFFFFFFF, mx, 2));
            float sum = 0.f;
#pragma unroll
            for (int ni = 0; ni < 13; ni++) {
                int c = ni * 8 + 2 * (l & 3);
                float e0 = 0.f, e1 = 0.f;
                if (c < 98) {
                    e0 = __expf(accS[t][ni][rr * 2 + 0] - mx);
                    e1 = __expf(accS[t][ni][rr * 2 + 1] - mx);
                }
                sum += e0 + e1;
                uint32_t pk = packh2(__float2half(e0), __float2half(e1));
                asm volatile("st.shared.b32 [%0], %1;"
                             :: "r"(sb + OP + (uint32_t)(r * 240 + c * 2)), "r"(pk)
                             : "memory");
            }
            sum += __shfl_xor_sync(0xFFFFFFFF, sum, 1);
            sum += __shfl_xor_sync(0xFFFFFFFF, sum, 2);
            invv[t][rr] = 1.f / sum;
        }
    }
    __syncthreads();

    float accO[2][4][4];
#pragma unroll
    for (int t = 0; t < 2; t++)
#pragma unroll
        for (int n = 0; n < 4; n++)
#pragma unroll
            for (int c = 0; c < 4; c++) accO[t][n][c] = 0.f;

#pragma unroll
    for (int kst = 0; kst < 7; kst++) {
        uint32_t aO[2][4];
#pragma unroll
        for (int t = 0; t < 2; t++) {
            int mt = wid * 2 + t;
            if (mt < 7) {
                uint32_t ad = sb + OP + (uint32_t)(mt * 16 + (l & 15)) * 240
                            + (uint32_t)(kst * 2 + (l >> 4)) * 16;
                ldsm4(aO[t][0], aO[t][1], aO[t][2], aO[t][3], ad);
            }
        }
        uint32_t bO[4][2];
#pragma unroll
        for (int half = 0; half < 2; half++) {
            uint32_t bd = sb + OV
                        + (uint32_t)(kst * 16 + (l & 7) + ((l >> 3) & 1) * 8) * 80
                        + (uint32_t)((l >> 4) * 8 + half * 16) * 2;
            uint32_t r0, r1, r2, r3;
            ldsm4t(r0, r1, r2, r3, bd);
            bO[2*half][0] = r0;   bO[2*half][1] = r1;
            bO[2*half+1][0] = r2; bO[2*half+1][1] = r3;
        }
#pragma unroll
        for (int t = 0; t < 2; t++) {
            int mt = wid * 2 + t;
            if (mt < 7)
#pragma unroll
                for (int ni = 0; ni < 4; ni++)
                    mma4(accO[t][ni], aO[t], bO[ni]);
        }
    }

#pragma unroll
    for (int t = 0; t < 2; t++) {
        int mt = wid * 2 + t;
        if (mt >= 7) continue;
#pragma unroll
        for (int rr = 0; rr < 2; rr++) {
            int r = mt * 16 + (l >> 2) + rr * 8;
            if (r >= 98) continue;
            float inv = invv[t][rr];
            __half* orow = g_ah + ((size_t)b * Nn + r) * DIM + h * HD;
#pragma unroll
            for (int ni = 0; ni < 4; ni++) {
                int c = ni * 8 + 2 * (l & 3);
                *(__half2*)(orow + c) =
                    __floats2half2_rn(accO[t][ni][rr * 2 + 0] * inv,
                                      accO[t][ni][rr * 2 + 1] * inv);
            }
        }
    }
}

// ---------------- launch -----------------------------------------------------
extern "C" void kernel_launch(void* const* d_in, const int* in_sizes, int n_in,
                              void* d_out, int out_size) {
    const float* x          = (const float*)d_in[0];
    const float* qkv_w      = (const float*)d_in[1];
    const float* qkv_b      = (const float*)d_in[2];
    const float* proj_w     = (const float*)d_in[3];
    const float* proj_b     = (const float*)d_in[4];
    const float* bias_table = (const float*)d_in[5];
    const int*   rel_index  = (const int*)d_in[6];
    float*       out        = (float*)d_out;

    static bool inited = false;
    if (!inited) {
        cudaFuncSetAttribute(gemm_kernel<true>,
                             cudaFuncAttributeMaxDynamicSharedMemorySize, SMEM_GEMM);
        cudaFuncSetAttribute(gemm_kernel<false>,
                             cudaFuncAttributeMaxDynamicSharedMemorySize, SMEM_GEMM);
        cudaFuncSetAttribute(attn_kernel,
                             cudaFuncAttributeMaxDynamicSharedMemorySize, SMEM_ATTN);
        inited = true;
    }

    conv_x_kernel<<<(int)((XELEMS / 4 + 255) / 256), 256>>>(x);
    prep_kernel<<<(PREP_TOT + 255) / 256, 256>>>(qkv_w, proj_w, bias_table, rel_index);
    gemm_kernel<true><<<dim3(QKV_N / 128, Mrows / 128), 256, SMEM_GEMM>>>(qkv_b, nullptr);
    attn_kernel<<<Bsz * NH, 128, SMEM_ATTN>>>();
    gemm_kernel<false><<<dim3(DIM / 128, Mrows / 128), 256, SMEM_GEMM>>>(proj_b, out);
}